// round 16
// baseline (speedup 1.0000x reference)
#include <cuda_runtime.h>
#include <cuda_bf16.h>
#include <cuda_fp16.h>
#include <math.h>
#include <stdint.h>

#define BATCH 8
#define CH    256
#define NPIX  4096
#define NBLK  32            // NPIX / 128 score blocks per row
#define BK    32

// Packed split format (u32 = hi | lo<<16) for W / X^T (qk2, v2 inputs).
static __device__ uint32_t g_wp[3 * CH * CH];
static __device__ uint32_t g_xt[(size_t)BATCH * NPIX * CH];
// Q^T/K^T: separate bf16 hi/lo planes, fragment-permuted within each k16 block.
static __device__ __half   g_qth[(size_t)BATCH * NPIX * CH];
static __device__ __half   g_qtl[(size_t)BATCH * NPIX * CH];
static __device__ __half   g_kth[(size_t)BATCH * NPIX * CH];
static __device__ __half   g_ktl[(size_t)BATCH * NPIX * CH];
static __device__ __half   g_vh[(size_t)BATCH * CH * NPIX];    // V fp16, k16-permuted
static __device__ __half   g_ah[(size_t)BATCH * NPIX * NPIX];  // p fp16, k16-permuted
static __device__ float    g_bm[(size_t)BATCH * NBLK * NPIX];
static __device__ float    g_bl[(size_t)BATCH * NBLK * NPIX];
static __device__ float    g_sc[(size_t)BATCH * NBLK * NPIX];

__device__ __forceinline__ uint32_t smem_u32(const void* p) {
    uint32_t a;
    asm("{ .reg .u64 t; cvta.to.shared.u64 t, %1; cvt.u32.u64 %0, t; }" : "=r"(a) : "l"(p));
    return a;
}
__device__ __forceinline__ uint32_t pack_split(float v) {
    __nv_bfloat16 h = __float2bfloat16(v);
    float r = v - __bfloat162float(h);
    __nv_bfloat16 l = __float2bfloat16(r);
    return (uint32_t)__bfloat16_as_ushort(h) | ((uint32_t)__bfloat16_as_ushort(l) << 16);
}
// split two values -> hi-pair u32 and lo-pair u32
__device__ __forceinline__ void split2(float v0, float v1, uint32_t& H, uint32_t& L) {
    __nv_bfloat16 h0 = __float2bfloat16(v0), h1 = __float2bfloat16(v1);
    __nv_bfloat16 l0 = __float2bfloat16(v0 - __bfloat162float(h0));
    __nv_bfloat16 l1 = __float2bfloat16(v1 - __bfloat162float(h1));
    H = (uint32_t)__bfloat16_as_ushort(h0) | ((uint32_t)__bfloat16_as_ushort(h1) << 16);
    L = (uint32_t)__bfloat16_as_ushort(l0) | ((uint32_t)__bfloat16_as_ushort(l1) << 16);
}
__device__ __forceinline__ void cp16(uint32_t saddr, const void* g) {
    uint64_t ga;
    asm("cvta.to.global.u64 %0, %1;" : "=l"(ga) : "l"(g));
    asm volatile("cp.async.cg.shared.global [%0], [%1], 16;" :: "r"(saddr), "l"(ga));
}
#define CP_COMMIT() asm volatile("cp.async.commit_group;" ::: "memory")
#define CP_WAIT1()  asm volatile("cp.async.wait_group 1;"  ::: "memory")
#define CP_WAIT0()  asm volatile("cp.async.wait_group 0;"  ::: "memory")
#define LDS64(a, b, addr) \
    asm volatile("ld.shared.v2.u32 {%0,%1}, [%2];" : "=r"(a), "=r"(b) : "r"(addr))
#define LDSF(a, addr) \
    asm volatile("ld.shared.f32 %0, [%1];" : "=f"(a) : "r"(addr))
#define MMAB(d, a, b0, b1)                                                        \
    asm volatile("mma.sync.aligned.m16n8k16.row.col.f32.bf16.bf16.f32 "           \
        "{%0,%1,%2,%3}, {%4,%5,%6,%7}, {%8,%9}, {%0,%1,%2,%3};"                   \
        : "+f"((d)[0]), "+f"((d)[1]), "+f"((d)[2]), "+f"((d)[3])                  \
        : "r"((a)[0]), "r"((a)[1]), "r"((a)[2]), "r"((a)[3]), "r"(b0), "r"(b1))
#define MMAH(d, a, b0, b1)                                                        \
    asm volatile("mma.sync.aligned.m16n8k16.row.col.f32.f16.f16.f32 "             \
        "{%0,%1,%2,%3}, {%4,%5,%6,%7}, {%8,%9}, {%0,%1,%2,%3};"                   \
        : "+f"((d)[0]), "+f"((d)[1]), "+f"((d)[2]), "+f"((d)[3])                  \
        : "r"((a)[0]), "r"((a)[1]), "r"((a)[2]), "r"((a)[3]), "r"(b0), "r"(b1))

// ---------------------------------------------------------------------------
// Packed-operand 128x128 GEMM machinery (qk2 / v2 inputs). Warp tile 64x32.
// ---------------------------------------------------------------------------
#define S2TILE 20480                        // 128 rows * 160B (packed) per matrix
#define S2BUF  (2 * S2TILE)                 // 40960
#define S2RED  (2 * S2BUF)
#define S2SMEM (S2RED + 4096)

__device__ __forceinline__ void load128(const uint32_t* __restrict__ Ag, int lda,
                                        const uint32_t* __restrict__ Bg, int ldb,
                                        uint32_t sbase, int tid) {
    #pragma unroll
    for (int i = 0; i < 4; i++) {
        int t = i * 256 + tid;
        int row = t >> 3, q = t & 7;
        cp16(sbase + (uint32_t)(row * 40 + q * 4) * 4, Ag + (size_t)row * lda + q * 4);
    }
    #pragma unroll
    for (int i = 0; i < 4; i++) {
        int t = i * 256 + tid;
        int row = t >> 3, q = t & 7;
        cp16(sbase + S2TILE + (uint32_t)(row * 40 + q * 4) * 4, Bg + (size_t)row * ldb + q * 4);
    }
}

__device__ __forceinline__ void gemm128_loop(const uint32_t* __restrict__ A, int lda,
                                             const uint32_t* __restrict__ B, int ldb,
                                             uint32_t smbase, int tid,
                                             int qrow, int qcol, int wm, int wn,
                                             int S, float (&acc)[4][4][4])
{
    load128(A, lda, B, ldb, smbase, tid);
    CP_COMMIT();

    #pragma unroll 1
    for (int s = 0; s < S; s++) {
        __syncthreads();
        if (s + 1 < S) {
            load128(A + (s + 1) * BK, lda, B + (s + 1) * BK, ldb,
                    smbase + (uint32_t)((s + 1) & 1) * S2BUF, tid);
            CP_COMMIT();
            CP_WAIT1();
        } else {
            CP_WAIT0();
        }
        __syncthreads();
        uint32_t sa = smbase + (uint32_t)(s & 1) * S2BUF;
        uint32_t sb = sa + S2TILE;
        #pragma unroll
        for (int ks = 0; ks < 2; ks++) {
            const int kc = ks * 16 + qcol * 2;
            uint32_t ah[4][4], al[4][4];
            #pragma unroll
            for (int mt = 0; mt < 4; mt++) {
                int r = wm * 64 + mt * 16 + qrow;
                uint32_t x0, x1, y0, y1, x2, x3, y2, y3;
                LDS64(x0, x1, sa + (uint32_t)(r * 40 + kc) * 4);
                LDS64(y0, y1, sa + (uint32_t)((r + 8) * 40 + kc) * 4);
                LDS64(x2, x3, sa + (uint32_t)(r * 40 + kc + 8) * 4);
                LDS64(y2, y3, sa + (uint32_t)((r + 8) * 40 + kc + 8) * 4);
                ah[mt][0] = __byte_perm(x0, x1, 0x5410); al[mt][0] = __byte_perm(x0, x1, 0x7632);
                ah[mt][1] = __byte_perm(y0, y1, 0x5410); al[mt][1] = __byte_perm(y0, y1, 0x7632);
                ah[mt][2] = __byte_perm(x2, x3, 0x5410); al[mt][2] = __byte_perm(x2, x3, 0x7632);
                ah[mt][3] = __byte_perm(y2, y3, 0x5410); al[mt][3] = __byte_perm(y2, y3, 0x7632);
            }
            #pragma unroll
            for (int nt = 0; nt < 4; nt++) {
                int r = wn * 32 + nt * 8 + qrow;
                uint32_t u0, u1, u2, u3;
                LDS64(u0, u1, sb + (uint32_t)(r * 40 + kc) * 4);
                LDS64(u2, u3, sb + (uint32_t)(r * 40 + kc + 8) * 4);
                uint32_t bh0 = __byte_perm(u0, u1, 0x5410), bh1 = __byte_perm(u2, u3, 0x5410);
                uint32_t bl0 = __byte_perm(u0, u1, 0x7632), bl1 = __byte_perm(u2, u3, 0x7632);
                #pragma unroll
                for (int mt = 0; mt < 4; mt++) {
                    MMAB(acc[mt][nt], ah[mt], bh0, bh1);
                    MMAB(acc[mt][nt], ah[mt], bl0, bl1);
                    MMAB(acc[mt][nt], al[mt], bh0, bh1);
                }
            }
        }
    }
}

// ---------------------------------------------------------------------------
// Q/K projections merged: z = b*2 + which. Output: hi/lo planes, k16-permuted.
// ---------------------------------------------------------------------------
__global__ __launch_bounds__(256, 2)
void qk2_kernel(const float* __restrict__ bq, const float* __restrict__ bk)
{
    extern __shared__ __align__(16) uint32_t smraw[];
    const uint32_t smbase = smem_u32(smraw);
    const int tid = threadIdx.x;
    const int lane = tid & 31, wid = tid >> 5;
    const int wm = wid >> 2, wn = wid & 3;
    const int z = blockIdx.z;
    const int b = z >> 1, which = z & 1;
    const int bm = blockIdx.y * 128, bn = blockIdx.x * 128;
    const int qrow = lane >> 2, qcol = lane & 3;

    const uint32_t* A = g_xt + (size_t)b * NPIX * CH + (size_t)bm * CH;
    const uint32_t* B = g_wp + (size_t)which * CH * CH + (size_t)bn * CH;
    __half* DstH = (which ? g_kth : g_qth) + (size_t)b * NPIX * CH;
    __half* DstL = (which ? g_ktl : g_qtl) + (size_t)b * NPIX * CH;
    const float* bias = which ? bk : bq;

    float acc[4][4][4];
    #pragma unroll
    for (int i = 0; i < 4; i++)
        #pragma unroll
        for (int j = 0; j < 4; j++)
            #pragma unroll
            for (int v = 0; v < 4; v++) acc[i][j][v] = 0.f;

    gemm128_loop(A, CH, B, CH, smbase, tid, qrow, qcol, wm, wn, CH / BK, acc);

    // Epilogue: write hi/lo planes in k16-fragment-permuted order.
    #pragma unroll
    for (int blk = 0; blk < 2; blk++) {
        const int n0 = 2 * blk, n1 = 2 * blk + 1;
        int colg = bn + wn * 32 + blk * 16 + qcol * 4;        // permuted half index
        int c00 = bn + wn * 32 + n0 * 8 + qcol * 2;           // orig bias cols
        int c10 = bn + wn * 32 + n1 * 8 + qcol * 2;
        float b00 = bias[c00], b01 = bias[c00 + 1];
        float b10 = bias[c10], b11 = bias[c10 + 1];
        #pragma unroll
        for (int mt = 0; mt < 4; mt++) {
            int r0 = bm + wm * 64 + mt * 16 + qrow;
            uint32_t H0, L0, H1, L1;
            // row r0
            split2(acc[mt][n0][0] + b00, acc[mt][n0][1] + b01, H0, L0);
            split2(acc[mt][n1][0] + b10, acc[mt][n1][1] + b11, H1, L1);
            *(uint2*)&DstH[(size_t)r0 * CH + colg] = make_uint2(H0, H1);
            *(uint2*)&DstL[(size_t)r0 * CH + colg] = make_uint2(L0, L1);
            // row r0+8
            split2(acc[mt][n0][2] + b00, acc[mt][n0][3] + b01, H0, L0);
            split2(acc[mt][n1][2] + b10, acc[mt][n1][3] + b11, H1, L1);
            *(uint2*)&DstH[(size_t)(r0 + 8) * CH + colg] = make_uint2(H0, H1);
            *(uint2*)&DstL[(size_t)(r0 + 8) * CH + colg] = make_uint2(L0, L1);
        }
    }
}

// ---------------------------------------------------------------------------
// V projection: D[c][n] fp16 + bias[c], k16-permuted (R15-proven).
// ---------------------------------------------------------------------------
__global__ __launch_bounds__(256, 2)
void v2_kernel(const float* __restrict__ bv)
{
    extern __shared__ __align__(16) uint32_t smraw[];
    const uint32_t smbase = smem_u32(smraw);
    const int tid = threadIdx.x;
    const int lane = tid & 31, wid = tid >> 5;
    const int wm = wid >> 2, wn = wid & 3;
    const int b = blockIdx.z;
    const int bm = blockIdx.y * 128, bn = blockIdx.x * 128;
    const int qrow = lane >> 2, qcol = lane & 3;

    const uint32_t* A = g_wp + (size_t)2 * CH * CH + (size_t)bm * CH;
    const uint32_t* B = g_xt + (size_t)b * NPIX * CH + (size_t)bn * CH;
    __half* Dst = g_vh + (size_t)b * CH * NPIX;

    float acc[4][4][4];
    #pragma unroll
    for (int i = 0; i < 4; i++)
        #pragma unroll
        for (int j = 0; j < 4; j++)
            #pragma unroll
            for (int v = 0; v < 4; v++) acc[i][j][v] = 0.f;

    gemm128_loop(A, CH, B, CH, smbase, tid, qrow, qcol, wm, wn, CH / BK, acc);

    #pragma unroll
    for (int blk = 0; blk < 2; blk++) {
        int colg = bn + wn * 32 + blk * 16 + qcol * 4;
        const int n0 = 2 * blk, n1 = 2 * blk + 1;
        #pragma unroll
        for (int mt = 0; mt < 4; mt++) {
            int r0 = bm + wm * 64 + mt * 16 + qrow;
            float b0 = bv[r0], b8 = bv[r0 + 8];
            __half2 x01 = __floats2half2_rn(acc[mt][n0][0] + b0, acc[mt][n0][1] + b0);
            __half2 y01 = __floats2half2_rn(acc[mt][n1][0] + b0, acc[mt][n1][1] + b0);
            __half2 x23 = __floats2half2_rn(acc[mt][n0][2] + b8, acc[mt][n0][3] + b8);
            __half2 y23 = __floats2half2_rn(acc[mt][n1][2] + b8, acc[mt][n1][3] + b8);
            *(uint2*)&Dst[(size_t)r0 * NPIX + colg] =
                make_uint2(*(uint32_t*)&x01, *(uint32_t*)&y01);
            *(uint2*)&Dst[(size_t)(r0 + 8) * NPIX + colg] =
                make_uint2(*(uint32_t*)&x23, *(uint32_t*)&y23);
        }
    }
}

// ---------------------------------------------------------------------------
// Scores GEMM on hi/lo plane operands (no PRMT) + fused block-softmax.
// Tile layout per stage: Ah | Al | Bh | Bl, each 128 rows x 64B @ 80B stride.
// ---------------------------------------------------------------------------
__device__ __forceinline__ void load_s3(const __half* __restrict__ Ah,
                                        const __half* __restrict__ Al,
                                        const __half* __restrict__ Bh,
                                        const __half* __restrict__ Bl,
                                        uint32_t sbase, int tid) {
    #pragma unroll
    for (int i = 0; i < 2; i++) {
        int t = i * 256 + tid;          // 0..511
        int row = t >> 2, q = t & 3;
        uint32_t d = sbase + (uint32_t)(row * 80 + q * 16);
        const size_t go = (size_t)row * CH + q * 8;
        cp16(d,         Ah + go);
        cp16(d + 10240, Al + go);
        cp16(d + 20480, Bh + go);
        cp16(d + 30720, Bl + go);
    }
}

__global__ __launch_bounds__(256, 2)
void scores2_kernel()
{
    extern __shared__ __align__(16) uint32_t smraw[];
    const uint32_t smbase = smem_u32(smraw);
    const int tid = threadIdx.x;
    const int lane = tid & 31, wid = tid >> 5;
    const int wm = wid >> 2, wn = wid & 3;
    const int z = blockIdx.z;
    const int bm = blockIdx.y * 128, bn = blockIdx.x * 128;
    const int jb = blockIdx.x;
    const int qrow = lane >> 2, qcol = lane & 3;

    const __half* Ah = g_qth + (size_t)z * NPIX * CH + (size_t)bm * CH;
    const __half* Al = g_qtl + (size_t)z * NPIX * CH + (size_t)bm * CH;
    const __half* Bh = g_kth + (size_t)z * NPIX * CH + (size_t)bn * CH;
    const __half* Bl = g_ktl + (size_t)z * NPIX * CH + (size_t)bn * CH;

    float acc[4][4][4];
    #pragma unroll
    for (int i = 0; i < 4; i++)
        #pragma unroll
        for (int j = 0; j < 4; j++)
            #pragma unroll
            for (int v = 0; v < 4; v++) acc[i][j][v] = 0.f;

    const int S = CH / BK;   // 8
    load_s3(Ah, Al, Bh, Bl, smbase, tid);
    CP_COMMIT();

    #pragma unroll 1
    for (int s = 0; s < S; s++) {
        __syncthreads();
        if (s + 1 < S) {
            load_s3(Ah + (s + 1) * BK, Al + (s + 1) * BK,
                    Bh + (s + 1) * BK, Bl + (s + 1) * BK,
                    smbase + (uint32_t)((s + 1) & 1) * S2BUF, tid);
            CP_COMMIT();
            CP_WAIT1();
        } else {
            CP_WAIT0();
        }
        __syncthreads();
        uint32_t saH = smbase + (uint32_t)(s & 1) * S2BUF;
        uint32_t saL = saH + 10240;
        uint32_t sbH = saH + 20480;
        uint32_t sbL = saH + 30720;
        #pragma unroll
        for (int ks = 0; ks < 2; ks++) {
            const uint32_t fo = (uint32_t)(ks * 32 + qcol * 8);
            uint32_t ah[4][4], al[4][4];
            #pragma unroll
            for (int mt = 0; mt < 4; mt++) {
                int r = wm * 64 + mt * 16 + qrow;
                LDS64(ah[mt][0], ah[mt][2], saH + (uint32_t)(r * 80) + fo);
                LDS64(ah[mt][1], ah[mt][3], saH + (uint32_t)((r + 8) * 80) + fo);
                LDS64(al[mt][0], al[mt][2], saL + (uint32_t)(r * 80) + fo);
                LDS64(al[mt][1], al[mt][3], saL + (uint32_t)((r + 8) * 80) + fo);
            }
            #pragma unroll
            for (int nt = 0; nt < 4; nt++) {
                int r = wn * 32 + nt * 8 + qrow;
                uint32_t bh0, bh1, bl0, bl1;
                LDS64(bh0, bh1, sbH + (uint32_t)(r * 80) + fo);
                LDS64(bl0, bl1, sbL + (uint32_t)(r * 80) + fo);
                #pragma unroll
                for (int mt = 0; mt < 4; mt++) {
                    MMAB(acc[mt][nt], ah[mt], bh0, bh1);
                    MMAB(acc[mt][nt], ah[mt], bl0, bl1);
                    MMAB(acc[mt][nt], al[mt], bh0, bh1);
                }
            }
        }
    }

    // ---- fused block-softmax epilogue (p written k16-permuted) ----
    float* redm = (float*)smraw + (S2RED >> 2);
    float* redl = redm + 512;

    float mrow[4][2];
    #pragma unroll
    for (int mt = 0; mt < 4; mt++)
        #pragma unroll
        for (int h = 0; h < 2; h++) {
            float v = -1e30f;
            #pragma unroll
            for (int nt = 0; nt < 4; nt++)
                v = fmaxf(v, fmaxf(acc[mt][nt][h * 2], acc[mt][nt][h * 2 + 1]));
            v = fmaxf(v, __shfl_xor_sync(0xffffffffu, v, 1));
            v = fmaxf(v, __shfl_xor_sync(0xffffffffu, v, 2));
            mrow[mt][h] = v;
            if (qcol == 0)
                redm[wn * 128 + wm * 64 + mt * 16 + qrow + h * 8] = v;
        }
    __syncthreads();
    #pragma unroll
    for (int mt = 0; mt < 4; mt++)
        #pragma unroll
        for (int h = 0; h < 2; h++) {
            int lr = wm * 64 + mt * 16 + qrow + h * 8;
            mrow[mt][h] = fmaxf(fmaxf(redm[lr], redm[128 + lr]),
                                fmaxf(redm[256 + lr], redm[384 + lr]));
        }

    __half* Pb = g_ah + (size_t)z * NPIX * NPIX;
    float ls[4][2] = {{0.f,0.f},{0.f,0.f},{0.f,0.f},{0.f,0.f}};
    #pragma unroll
    for (int blk = 0; blk < 2; blk++) {
        int colg = bn + wn * 32 + blk * 16 + qcol * 4;
        const int n0 = 2 * blk, n1 = 2 * blk + 1;
        #pragma unroll
        for (int mt = 0; mt < 4; mt++) {
            int r0 = bm + wm * 64 + mt * 16 + qrow;
            float p0 = __expf(acc[mt][n0][0] - mrow[mt][0]);
            float p1 = __expf(acc[mt][n0][1] - mrow[mt][0]);
            float p2 = __expf(acc[mt][n0][2] - mrow[mt][1]);
            float p3 = __expf(acc[mt][n0][3] - mrow[mt][1]);
            float q0 = __expf(acc[mt][n1][0] - mrow[mt][0]);
            float q1 = __expf(acc[mt][n1][1] - mrow[mt][0]);
            float q2 = __expf(acc[mt][n1][2] - mrow[mt][1]);
            float q3 = __expf(acc[mt][n1][3] - mrow[mt][1]);
            ls[mt][0] += p0 + p1 + q0 + q1;
            ls[mt][1] += p2 + p3 + q2 + q3;
            __half2 a01 = __floats2half2_rn(p0, p1), b01 = __floats2half2_rn(q0, q1);
            __half2 a23 = __floats2half2_rn(p2, p3), b23 = __floats2half2_rn(q2, q3);
            *(uint2*)&Pb[(size_t)r0 * NPIX + colg] =
                make_uint2(*(uint32_t*)&a01, *(uint32_t*)&b01);
            *(uint2*)&Pb[(size_t)(r0 + 8) * NPIX + colg] =
                make_uint2(*(uint32_t*)&a23, *(uint32_t*)&b23);
        }
    }
    #pragma unroll
    for (int mt = 0; mt < 4; mt++)
        #pragma unroll
        for (int h = 0; h < 2; h++) {
            float v = ls[mt][h];
            v += __shfl_xor_sync(0xffffffffu, v, 1);
            v += __shfl_xor_sync(0xffffffffu, v, 2);
            if (qcol == 0)
                redl[wn * 128 + wm * 64 + mt * 16 + qrow + h * 8] = v;
        }
    __syncthreads();
    if (wn == 0 && qcol == 0) {
        float* BM_ = g_bm + ((size_t)z * NBLK + jb) * NPIX + bm;
        float* BL_ = g_bl + ((size_t)z * NBLK + jb) * NPIX + bm;
        #pragma unroll
        for (int mt = 0; mt < 4; mt++)
            #pragma unroll
            for (int h = 0; h < 2; h++) {
                int lr = wm * 64 + mt * 16 + qrow + h * 8;
                BM_[lr] = mrow[mt][h];
                BL_[lr] = redl[lr] + redl[128 + lr] + redl[256 + lr] + redl[384 + lr];
            }
    }
}

// ---------------------------------------------------------------------------
// Row stats: scale[z][jb][i] = exp(m_b - m_g) / tot
// ---------------------------------------------------------------------------
__global__ __launch_bounds__(256) void rowstats_kernel()
{
    int t = blockIdx.x * 256 + threadIdx.x;
    int z = t >> 12, i = t & (NPIX - 1);
    size_t base = (size_t)z * NBLK * NPIX + i;

    float mv[NBLK];
    float mg = -1e30f;
    #pragma unroll
    for (int jb = 0; jb < NBLK; jb++) {
        mv[jb] = g_bm[base + (size_t)jb * NPIX];
        mg = fmaxf(mg, mv[jb]);
    }
    float tot = 0.f;
    #pragma unroll
    for (int jb = 0; jb < NBLK; jb++)
        tot += g_bl[base + (size_t)jb * NPIX] * __expf(mv[jb] - mg);
    float inv = 1.0f / tot;
    #pragma unroll
    for (int jb = 0; jb < NBLK; jb++)
        g_sc[base + (size_t)jb * NPIX] = __expf(mv[jb] - mg) * inv;
}

// ---------------------------------------------------------------------------
// AV GEMM with in-loop normalization; k16-permuted fragment-order operands.
// ---------------------------------------------------------------------------
#define AVTILE 10240
#define AVBUF  (2 * AVTILE)
#define AVSC   (3 * AVBUF)
#define AVSMEM (AVSC + NBLK * 128 * 4)

__device__ __forceinline__ void load_av2(const __half* __restrict__ Ag,
                                         const __half* __restrict__ Bg,
                                         uint32_t sbase, int tid) {
    #pragma unroll
    for (int i = 0; i < 2; i++) {
        int t = i * 256 + tid;
        int row = t >> 2, q = t & 3;
        cp16(sbase + (uint32_t)(row * 80 + q * 16), Ag + (size_t)row * NPIX + q * 8);
    }
    #pragma unroll
    for (int i = 0; i < 2; i++) {
        int t = i * 256 + tid;
        int row = t >> 2, q = t & 3;
        cp16(sbase + AVTILE + (uint32_t)(row * 80 + q * 16), Bg + (size_t)row * NPIX + q * 8);
    }
}

__global__ __launch_bounds__(256, 2)
void av3_kernel(const __half* __restrict__ A,
                const __half* __restrict__ B,
                float* __restrict__ D)
{
    extern __shared__ __align__(16) uint32_t smraw[];
    const uint32_t smbase = smem_u32(smraw);
    const int tid = threadIdx.x;
    const int lane = tid & 31, wid = tid >> 5;
    const int wm = wid >> 2, wn = wid & 3;
    const int z = blockIdx.z;
    const int bm = blockIdx.y * 128, bn = blockIdx.x * 128;

    A += (size_t)z * CH * NPIX + (size_t)bm * NPIX;
    B += (size_t)z * NPIX * NPIX + (size_t)bn * NPIX;
    D += (size_t)z * CH * NPIX;

    {
        const float* SC = g_sc + (size_t)z * NBLK * NPIX + bn;
        float* sdst = (float*)smraw + (AVSC >> 2);
        #pragma unroll
        for (int t = 0; t < 16; t++) {
            int task = t * 256 + tid;
            int jbb = task >> 7, ii = task & 127;
            sdst[jbb * 128 + ii] = SC[(size_t)jbb * NPIX + ii];
        }
    }

    float acc[4][4][4];
    #pragma unroll
    for (int i = 0; i < 4; i++)
        #pragma unroll
        for (int j = 0; j < 4; j++)
            #pragma unroll
            for (int v = 0; v < 4; v++) acc[i][j][v] = 0.f;

    const int qrow = lane >> 2, qcol = lane & 3;
    const int S = NPIX / BK;   // 128

    load_av2(A, B, smbase, tid);
    CP_COMMIT();
    load_av2(A + BK, B + BK, smbase + AVBUF, tid);
    CP_COMMIT();

    uint32_t sreg[4];

    #pragma unroll 1
    for (int s = 0; s < S; s++) {
        CP_WAIT1();
        __syncthreads();
        if (s + 2 < S)
            load_av2(A + (s + 2) * BK, B + (s + 2) * BK,
                     smbase + (uint32_t)((s + 2) % 3) * AVBUF, tid);
        CP_COMMIT();

        if ((s & 3) == 0) {
            int jbb = s >> 2;
            #pragma unroll
            for (int nt = 0; nt < 4; nt++) {
                int cr = wn * 32 + nt * 8 + qrow;
                float sv;
                LDSF(sv, smbase + AVSC + (uint32_t)(jbb * 128 + cr) * 4);
                __half2 h2 = __float2half2_rn(sv);
                sreg[nt] = *(uint32_t*)&h2;
            }
        }

        uint32_t sa = smbase + (uint32_t)(s % 3) * AVBUF;
        uint32_t sb = sa + AVTILE;
        #pragma unroll
        for (int ks = 0; ks < 2; ks++) {
            const uint32_t fo = (uint32_t)(ks * 32 + qcol * 8);
            uint32_t af[4][4];
            #pragma unroll
            for (int mt = 0; mt < 4; mt++) {
                int r = wm * 64 + mt * 16 + qrow;
                LDS64(af[mt][0], af[mt][2], sa + (uint32_t)(r * 80) + fo);
                LDS64(af[mt][1], af[mt][3], sa + (uint32_t)((r + 8) * 80) + fo);
            }
            #pragma unroll
            for (int nt = 0; nt < 4; nt++) {
                int cr = wn * 32 + nt * 8 + qrow;
                uint32_t b0, b1;
                LDS64(b0, b1, sb + (uint32_t)(cr * 80) + fo);
                __half2 hb0 = __hmul2(*(__half2*)&b0, *(__half2*)&sreg[nt]);
                __half2 hb1 = __hmul2(*(__half2*)&b1, *(__half2*)&sreg[nt]);
                b0 = *(uint32_t*)&hb0;
                b1 = *(uint32_t*)&hb1;
                #pragma unroll
                for (int mt = 0; mt < 4; mt++)
                    MMAH(acc[mt][nt], af[mt], b0, b1);
            }
        }
    }

    #pragma unroll
    for (int nt = 0; nt < 4; nt++) {
        int col = bn + wn * 32 + nt * 8 + qcol * 2;
        #pragma unroll
        for (int mt = 0; mt < 4; mt++) {
            int r0 = bm + wm * 64 + mt * 16 + qrow;
            *(float2*)&D[(size_t)r0 * NPIX + col] =
                make_float2(acc[mt][nt][0], acc[mt][nt][1]);
            *(float2*)&D[(size_t)(r0 + 8) * NPIX + col] =
                make_float2(acc[mt][nt][2], acc[mt][nt][3]);
        }
    }
}

// ---------------------------------------------------------------------------
// Packing kernels
// ---------------------------------------------------------------------------
__global__ __launch_bounds__(256) void pack_w_kernel(
    const float* __restrict__ wq, const float* __restrict__ wk,
    const float* __restrict__ wv)
{
    int i = blockIdx.x * 256 + threadIdx.x;
    g_wp[i]               = pack_split(wq[i]);
    g_wp[CH * CH + i]     = pack_split(wk[i]);
    g_wp[2 * CH * CH + i] = pack_split(wv[i]);
}

__global__ __launch_bounds__(256) void pack_xt_kernel(const float* __restrict__ x)
{
    __shared__ float t[32][33];
    const int b = blockIdx.z;
    const int n0 = blockIdx.x * 32, c0 = blockIdx.y * 32;
    const int tx = threadIdx.x, ty = threadIdx.y;
    const float* xb = x + (size_t)b * CH * NPIX;
    #pragma unroll
    for (int i = 0; i < 4; i++)
        t[ty * 4 + i][tx] = xb[(size_t)(c0 + ty * 4 + i) * NPIX + n0 + tx];
    __syncthreads();
    uint32_t* xt = g_xt + (size_t)b * NPIX * CH;
    #pragma unroll
    for (int i = 0; i < 4; i++)
        xt[(size_t)(n0 + ty * 4 + i) * CH + c0 + tx] = pack_split(t[tx][ty * 4 + i]);
}

// ---------------------------------------------------------------------------
extern "C" void kernel_launch(void* const* d_in, const int* in_sizes, int n_in,
                              void* d_out, int out_size)
{
    const float* x  = (const float*)d_in[0];
    const float* wq = (const float*)d_in[1];
    const float* bq = (const float*)d_in[2];
    const float* wk = (const float*)d_in[3];
    const float* bk = (const float*)d_in[4];
    const float* wv = (const float*)d_in[5];
    const float* bv = (const float*)d_in[6];
    float* out = (float*)d_out;

    void *pvh, *pah;
    cudaGetSymbolAddress(&pvh, g_vh);
    cudaGetSymbolAddress(&pah, g_ah);
    __half* vh = (__half*)pvh;
    __half* ah = (__half*)pah;

    cudaFuncSetAttribute(qk2_kernel,     cudaFuncAttributeMaxDynamicSharedMemorySize, S2SMEM);
    cudaFuncSetAttribute(v2_kernel,      cudaFuncAttributeMaxDynamicSharedMemorySize, S2SMEM);
    cudaFuncSetAttribute(scores2_kernel, cudaFuncAttributeMaxDynamicSharedMemorySize, S2SMEM);
    cudaFuncSetAttribute(av3_kernel,     cudaFuncAttributeMaxDynamicSharedMemorySize, AVSMEM);

    pack_w_kernel<<<CH * CH / 256, 256>>>(wq, wk, wv);
    pack_xt_kernel<<<dim3(NPIX / 32, CH / 32, BATCH), dim3(32, 8)>>>(x);

    // Q^T and K^T projections merged -> hi/lo fragment-permuted planes
    qk2_kernel<<<dim3(CH / 128, NPIX / 128, BATCH * 2), 256, S2SMEM>>>(bq, bk);
    // V[c][n] fp16 (k16-permuted)
    v2_kernel<<<dim3(NPIX / 128, CH / 128, BATCH), 256, S2SMEM>>>(bv);
    // scores (PRMT-free plane mainloop) + fused block softmax
    scores2_kernel<<<dim3(NPIX / 128, NPIX / 128, BATCH), 256, S2SMEM>>>();
    // per-row global stats -> scale
    rowstats_kernel<<<BATCH * NPIX / 256, 256>>>();
    // out[c][i] = sum_j V[c][j] * p[i][j] * scale
    av3_kernel<<<dim3(NPIX / 128, CH / 128, BATCH), 256, AVSMEM>>>(vh, ah, out);
}

// round 17
// speedup vs baseline: 1.2206x; 1.2206x over previous
#include <cuda_runtime.h>
#include <cuda_bf16.h>
#include <cuda_fp16.h>
#include <math.h>
#include <stdint.h>

#define BATCH 8
#define CH    256
#define NPIX  4096
#define NBLK  32            // NPIX / 128 score blocks per row
#define BK    32

// Packed split formats: u32 = lo16(hi) | lo16(lo)<<16, value ~= hi + lo
static __device__ uint32_t g_wp[3 * CH * CH];                  // packed bf16 wq|wk|wv
static __device__ uint32_t g_xt[(size_t)BATCH * NPIX * CH];    // x^T  [b][n][c] bf16-split
static __device__ uint32_t g_qt[(size_t)BATCH * NPIX * CH];    // Q^T  [b][n][c] bf16-split
static __device__ uint32_t g_kt[(size_t)BATCH * NPIX * CH];    // K^T  [b][n][c] bf16-split
static __device__ __half   g_vh[(size_t)BATCH * CH * NPIX];    // V    [b][c][n] fp16 single
static __device__ __half   g_ah[(size_t)BATCH * NPIX * NPIX];  // p fp16 [b][i][j]
static __device__ float    g_bm[(size_t)BATCH * NBLK * NPIX];  // block row max
static __device__ float    g_bl[(size_t)BATCH * NBLK * NPIX];  // block row sum
static __device__ float    g_sc[(size_t)BATCH * NBLK * NPIX];  // scale

__device__ __forceinline__ uint32_t smem_u32(const void* p) {
    uint32_t a;
    asm("{ .reg .u64 t; cvta.to.shared.u64 t, %1; cvt.u32.u64 %0, t; }" : "=r"(a) : "l"(p));
    return a;
}
__device__ __forceinline__ uint32_t pack_split(float v) {
    __nv_bfloat16 h = __float2bfloat16(v);
    float r = v - __bfloat162float(h);
    __nv_bfloat16 l = __float2bfloat16(r);
    return (uint32_t)__bfloat16_as_ushort(h) | ((uint32_t)__bfloat16_as_ushort(l) << 16);
}
__device__ __forceinline__ void cp16(uint32_t saddr, const void* g) {
    uint64_t ga;
    asm("cvta.to.global.u64 %0, %1;" : "=l"(ga) : "l"(g));
    asm volatile("cp.async.cg.shared.global [%0], [%1], 16;" :: "r"(saddr), "l"(ga));
}
#define CP_COMMIT() asm volatile("cp.async.commit_group;" ::: "memory")
#define CP_WAIT1()  asm volatile("cp.async.wait_group 1;"  ::: "memory")
#define CP_WAIT0()  asm volatile("cp.async.wait_group 0;"  ::: "memory")
#define LDS64(a, b, addr) \
    asm volatile("ld.shared.v2.u32 {%0,%1}, [%2];" : "=r"(a), "=r"(b) : "r"(addr))
#define LDS32(a, addr) \
    asm volatile("ld.shared.u32 %0, [%1];" : "=r"(a) : "r"(addr))
#define LDSF(a, addr) \
    asm volatile("ld.shared.f32 %0, [%1];" : "=f"(a) : "r"(addr))
#define MMAB(d, a, b0, b1)                                                        \
    asm volatile("mma.sync.aligned.m16n8k16.row.col.f32.bf16.bf16.f32 "           \
        "{%0,%1,%2,%3}, {%4,%5,%6,%7}, {%8,%9}, {%0,%1,%2,%3};"                   \
        : "+f"((d)[0]), "+f"((d)[1]), "+f"((d)[2]), "+f"((d)[3])                  \
        : "r"((a)[0]), "r"((a)[1]), "r"((a)[2]), "r"((a)[3]), "r"(b0), "r"(b1))
#define MMAH(d, a, b0, b1)                                                        \
    asm volatile("mma.sync.aligned.m16n8k16.row.col.f32.f16.f16.f32 "             \
        "{%0,%1,%2,%3}, {%4,%5,%6,%7}, {%8,%9}, {%0,%1,%2,%3};"                   \
        : "+f"((d)[0]), "+f"((d)[1]), "+f"((d)[2]), "+f"((d)[3])                  \
        : "r"((a)[0]), "r"((a)[1]), "r"((a)[2]), "r"((a)[3]), "r"(b0), "r"(b1))

// ---------------------------------------------------------------------------
// Shared 128x128 2-CTA/SM GEMM machinery (R13-proven). Warp tile 64(m) x 32(n).
// 2-stage cp.async, BK=32, K-major packed u32.
// ---------------------------------------------------------------------------
#define S2TILE 20480                        // 128 rows * 40 u32 * 4B
#define S2BUF  (2 * S2TILE)                 // 40960
#define S2RED  (2 * S2BUF)
#define S2SMEM (S2RED + 4096)

__device__ __forceinline__ void load128(const uint32_t* __restrict__ Ag, int lda,
                                        const uint32_t* __restrict__ Bg, int ldb,
                                        uint32_t sbase, int tid) {
    #pragma unroll
    for (int i = 0; i < 4; i++) {
        int t = i * 256 + tid;
        int row = t >> 3, q = t & 7;
        cp16(sbase + (uint32_t)(row * 40 + q * 4) * 4, Ag + (size_t)row * lda + q * 4);
    }
    #pragma unroll
    for (int i = 0; i < 4; i++) {
        int t = i * 256 + tid;
        int row = t >> 3, q = t & 7;
        cp16(sbase + S2TILE + (uint32_t)(row * 40 + q * 4) * 4, Bg + (size_t)row * ldb + q * 4);
    }
}

__device__ __forceinline__ void gemm128_loop(const uint32_t* __restrict__ A, int lda,
                                             const uint32_t* __restrict__ B, int ldb,
                                             uint32_t smbase, int tid,
                                             int qrow, int qcol, int wm, int wn,
                                             int S, float (&acc)[4][4][4])
{
    load128(A, lda, B, ldb, smbase, tid);
    CP_COMMIT();

    #pragma unroll 1
    for (int s = 0; s < S; s++) {
        __syncthreads();
        if (s + 1 < S) {
            load128(A + (s + 1) * BK, lda, B + (s + 1) * BK, ldb,
                    smbase + (uint32_t)((s + 1) & 1) * S2BUF, tid);
            CP_COMMIT();
            CP_WAIT1();
        } else {
            CP_WAIT0();
        }
        __syncthreads();
        uint32_t sa = smbase + (uint32_t)(s & 1) * S2BUF;
        uint32_t sb = sa + S2TILE;
        #pragma unroll
        for (int ks = 0; ks < 2; ks++) {
            const int kc = ks * 16 + qcol * 2;
            uint32_t ah[4][4], al[4][4];
            #pragma unroll
            for (int mt = 0; mt < 4; mt++) {
                int r = wm * 64 + mt * 16 + qrow;
                uint32_t x0, x1, y0, y1, x2, x3, y2, y3;
                LDS64(x0, x1, sa + (uint32_t)(r * 40 + kc) * 4);
                LDS64(y0, y1, sa + (uint32_t)((r + 8) * 40 + kc) * 4);
                LDS64(x2, x3, sa + (uint32_t)(r * 40 + kc + 8) * 4);
                LDS64(y2, y3, sa + (uint32_t)((r + 8) * 40 + kc + 8) * 4);
                ah[mt][0] = __byte_perm(x0, x1, 0x5410); al[mt][0] = __byte_perm(x0, x1, 0x7632);
                ah[mt][1] = __byte_perm(y0, y1, 0x5410); al[mt][1] = __byte_perm(y0, y1, 0x7632);
                ah[mt][2] = __byte_perm(x2, x3, 0x5410); al[mt][2] = __byte_perm(x2, x3, 0x7632);
                ah[mt][3] = __byte_perm(y2, y3, 0x5410); al[mt][3] = __byte_perm(y2, y3, 0x7632);
            }
            #pragma unroll
            for (int nt = 0; nt < 4; nt++) {
                int r = wn * 32 + nt * 8 + qrow;
                uint32_t u0, u1, u2, u3;
                LDS64(u0, u1, sb + (uint32_t)(r * 40 + kc) * 4);
                LDS64(u2, u3, sb + (uint32_t)(r * 40 + kc + 8) * 4);
                uint32_t bh0 = __byte_perm(u0, u1, 0x5410), bh1 = __byte_perm(u2, u3, 0x5410);
                uint32_t bl0 = __byte_perm(u0, u1, 0x7632), bl1 = __byte_perm(u2, u3, 0x7632);
                #pragma unroll
                for (int mt = 0; mt < 4; mt++) {
                    MMAB(acc[mt][nt], ah[mt], bh0, bh1);
                    MMAB(acc[mt][nt], ah[mt], bl0, bl1);
                    MMAB(acc[mt][nt], al[mt], bh0, bh1);
                }
            }
        }
    }
}

// ---------------------------------------------------------------------------
// Merged projections: z = b*3 + which. which 0/1 = Q/K (out [n][c] packed +
// bias[col]); which 2 = V (out [c][n] fp16 + bias[row]). One launch, one tail.
// ---------------------------------------------------------------------------
__global__ __launch_bounds__(256, 2)
void proj_kernel(const float* __restrict__ bq, const float* __restrict__ bk,
                 const float* __restrict__ bv)
{
    extern __shared__ __align__(16) uint32_t smraw[];
    const uint32_t smbase = smem_u32(smraw);
    const int tid = threadIdx.x;
    const int lane = tid & 31, wid = tid >> 5;
    const int wm = wid >> 2, wn = wid & 3;
    const int z = blockIdx.z;
    const int b = z / 3, which = z % 3;
    const int qrow = lane >> 2, qcol = lane & 3;

    float acc[4][4][4];
    #pragma unroll
    for (int i = 0; i < 4; i++)
        #pragma unroll
        for (int j = 0; j < 4; j++)
            #pragma unroll
            for (int v = 0; v < 4; v++) acc[i][j][v] = 0.f;

    if (which < 2) {
        // Q/K: A = xt rows (pixels), B = w rows (out-channels)
        const int bm = blockIdx.x * 128;          // pixel tile (32)
        const int bn = blockIdx.y * 128;          // channel tile (2)
        const uint32_t* A = g_xt + (size_t)b * NPIX * CH + (size_t)bm * CH;
        const uint32_t* B = g_wp + (size_t)which * CH * CH + (size_t)bn * CH;
        uint32_t* Dst = (which ? g_kt : g_qt) + (size_t)b * NPIX * CH;
        const float* bias = which ? bk : bq;

        gemm128_loop(A, CH, B, CH, smbase, tid, qrow, qcol, wm, wn, CH / BK, acc);

        #pragma unroll
        for (int nt = 0; nt < 4; nt++) {
            int col = bn + wn * 32 + nt * 8 + qcol * 2;
            float bc0 = bias[col], bc1 = bias[col + 1];
            #pragma unroll
            for (int mt = 0; mt < 4; mt++) {
                int r0 = bm + wm * 64 + mt * 16 + qrow;
                uint32_t p0 = pack_split(acc[mt][nt][0] + bc0);
                uint32_t p1 = pack_split(acc[mt][nt][1] + bc1);
                uint32_t p2 = pack_split(acc[mt][nt][2] + bc0);
                uint32_t p3 = pack_split(acc[mt][nt][3] + bc1);
                *(uint2*)&Dst[(size_t)r0 * CH + col] = make_uint2(p0, p1);
                *(uint2*)&Dst[(size_t)(r0 + 8) * CH + col] = make_uint2(p2, p3);
            }
        }
    } else {
        // V: A = wv rows (out-channels), B = xt rows (pixels)
        const int bm = blockIdx.y * 128;          // channel tile (2)
        const int bn = blockIdx.x * 128;          // pixel tile (32)
        const uint32_t* A = g_wp + (size_t)2 * CH * CH + (size_t)bm * CH;
        const uint32_t* B = g_xt + (size_t)b * NPIX * CH + (size_t)bn * CH;
        __half* Dst = g_vh + (size_t)b * CH * NPIX;

        gemm128_loop(A, CH, B, CH, smbase, tid, qrow, qcol, wm, wn, CH / BK, acc);

        #pragma unroll
        for (int nt = 0; nt < 4; nt++) {
            int col = bn + wn * 32 + nt * 8 + qcol * 2;
            #pragma unroll
            for (int mt = 0; mt < 4; mt++) {
                int r0 = bm + wm * 64 + mt * 16 + qrow;
                float b0 = bv[r0], b8 = bv[r0 + 8];
                __half2 v01 = __floats2half2_rn(acc[mt][nt][0] + b0, acc[mt][nt][1] + b0);
                __half2 v23 = __floats2half2_rn(acc[mt][nt][2] + b8, acc[mt][nt][3] + b8);
                *(__half2*)&Dst[(size_t)r0 * NPIX + col] = v01;
                *(__half2*)&Dst[(size_t)(r0 + 8) * NPIX + col] = v23;
            }
        }
    }
}

// ---------------------------------------------------------------------------
// Scores GEMM with fused block-softmax epilogue (R13-proven).
// ---------------------------------------------------------------------------
__global__ __launch_bounds__(256, 2)
void scores2_kernel()
{
    extern __shared__ __align__(16) uint32_t smraw[];
    const uint32_t smbase = smem_u32(smraw);
    const int tid = threadIdx.x;
    const int lane = tid & 31, wid = tid >> 5;
    const int wm = wid >> 2, wn = wid & 3;
    const int z = blockIdx.z;
    const int bm = blockIdx.y * 128, bn = blockIdx.x * 128;
    const int jb = blockIdx.x;
    const int qrow = lane >> 2, qcol = lane & 3;

    const uint32_t* A = g_qt + (size_t)z * NPIX * CH + (size_t)bm * CH;
    const uint32_t* B = g_kt + (size_t)z * NPIX * CH + (size_t)bn * CH;

    float acc[4][4][4];
    #pragma unroll
    for (int i = 0; i < 4; i++)
        #pragma unroll
        for (int j = 0; j < 4; j++)
            #pragma unroll
            for (int v = 0; v < 4; v++) acc[i][j][v] = 0.f;

    gemm128_loop(A, CH, B, CH, smbase, tid, qrow, qcol, wm, wn, CH / BK, acc);

    // ---- fused block-softmax epilogue ----
    float* redm = (float*)smraw + (S2RED >> 2);
    float* redl = redm + 512;

    float mrow[4][2];
    #pragma unroll
    for (int mt = 0; mt < 4; mt++)
        #pragma unroll
        for (int h = 0; h < 2; h++) {
            float v = -1e30f;
            #pragma unroll
            for (int nt = 0; nt < 4; nt++)
                v = fmaxf(v, fmaxf(acc[mt][nt][h * 2], acc[mt][nt][h * 2 + 1]));
            v = fmaxf(v, __shfl_xor_sync(0xffffffffu, v, 1));
            v = fmaxf(v, __shfl_xor_sync(0xffffffffu, v, 2));
            mrow[mt][h] = v;
            if (qcol == 0)
                redm[wn * 128 + wm * 64 + mt * 16 + qrow + h * 8] = v;
        }
    __syncthreads();
    #pragma unroll
    for (int mt = 0; mt < 4; mt++)
        #pragma unroll
        for (int h = 0; h < 2; h++) {
            int lr = wm * 64 + mt * 16 + qrow + h * 8;
            mrow[mt][h] = fmaxf(fmaxf(redm[lr], redm[128 + lr]),
                                fmaxf(redm[256 + lr], redm[384 + lr]));
        }

    __half* Pb = g_ah + (size_t)z * NPIX * NPIX;
    float ls[4][2] = {{0.f,0.f},{0.f,0.f},{0.f,0.f},{0.f,0.f}};
    #pragma unroll
    for (int nt = 0; nt < 4; nt++) {
        int colg = bn + wn * 32 + nt * 8 + qcol * 2;
        #pragma unroll
        for (int mt = 0; mt < 4; mt++) {
            int r0 = bm + wm * 64 + mt * 16 + qrow;
            float p0 = __expf(acc[mt][nt][0] - mrow[mt][0]);
            float p1 = __expf(acc[mt][nt][1] - mrow[mt][0]);
            float p2 = __expf(acc[mt][nt][2] - mrow[mt][1]);
            float p3 = __expf(acc[mt][nt][3] - mrow[mt][1]);
            ls[mt][0] += p0 + p1;
            ls[mt][1] += p2 + p3;
            *(__half2*)&Pb[(size_t)r0 * NPIX + colg]       = __floats2half2_rn(p0, p1);
            *(__half2*)&Pb[(size_t)(r0 + 8) * NPIX + colg] = __floats2half2_rn(p2, p3);
        }
    }
    #pragma unroll
    for (int mt = 0; mt < 4; mt++)
        #pragma unroll
        for (int h = 0; h < 2; h++) {
            float v = ls[mt][h];
            v += __shfl_xor_sync(0xffffffffu, v, 1);
            v += __shfl_xor_sync(0xffffffffu, v, 2);
            if (qcol == 0)
                redl[wn * 128 + wm * 64 + mt * 16 + qrow + h * 8] = v;
        }
    __syncthreads();
    if (wn == 0 && qcol == 0) {
        float* BM_ = g_bm + ((size_t)z * NBLK + jb) * NPIX + bm;
        float* BL_ = g_bl + ((size_t)z * NBLK + jb) * NPIX + bm;
        #pragma unroll
        for (int mt = 0; mt < 4; mt++)
            #pragma unroll
            for (int h = 0; h < 2; h++) {
                int lr = wm * 64 + mt * 16 + qrow + h * 8;
                BM_[lr] = mrow[mt][h];
                BL_[lr] = redl[lr] + redl[128 + lr] + redl[256 + lr] + redl[384 + lr];
            }
    }
}

// ---------------------------------------------------------------------------
// Row stats: scale[z][jb][i] = exp(m_b - m_g) / tot
// ---------------------------------------------------------------------------
__global__ __launch_bounds__(256) void rowstats_kernel()
{
    int t = blockIdx.x * 256 + threadIdx.x;
    int z = t >> 12, i = t & (NPIX - 1);
    size_t base = (size_t)z * NBLK * NPIX + i;

    float mv[NBLK];
    float mg = -1e30f;
    #pragma unroll
    for (int jb = 0; jb < NBLK; jb++) {
        mv[jb] = g_bm[base + (size_t)jb * NPIX];
        mg = fmaxf(mg, mv[jb]);
    }
    float tot = 0.f;
    #pragma unroll
    for (int jb = 0; jb < NBLK; jb++)
        tot += g_bl[base + (size_t)jb * NPIX] * __expf(mv[jb] - mg);
    float inv = 1.0f / tot;
    #pragma unroll
    for (int jb = 0; jb < NBLK; jb++)
        g_sc[base + (size_t)jb * NPIX] = __expf(mv[jb] - mg) * inv;
}

// ---------------------------------------------------------------------------
// AV GEMM with in-loop normalization (R13-proven, LDS32 fragment loads).
// ---------------------------------------------------------------------------
#define AVTILE 10240
#define AVBUF  (2 * AVTILE)
#define AVSC   (3 * AVBUF)
#define AVSMEM (AVSC + NBLK * 128 * 4)

__device__ __forceinline__ void load_av2(const __half* __restrict__ Ag,
                                         const __half* __restrict__ Bg,
                                         uint32_t sbase, int tid) {
    #pragma unroll
    for (int i = 0; i < 2; i++) {
        int t = i * 256 + tid;
        int row = t >> 2, q = t & 3;
        cp16(sbase + (uint32_t)(row * 80 + q * 16), Ag + (size_t)row * NPIX + q * 8);
    }
    #pragma unroll
    for (int i = 0; i < 2; i++) {
        int t = i * 256 + tid;
        int row = t >> 2, q = t & 3;
        cp16(sbase + AVTILE + (uint32_t)(row * 80 + q * 16), Bg + (size_t)row * NPIX + q * 8);
    }
}

__global__ __launch_bounds__(256, 2)
void av3_kernel(const __half* __restrict__ A,
                const __half* __restrict__ B,
                float* __restrict__ D)
{
    extern __shared__ __align__(16) uint32_t smraw[];
    const uint32_t smbase = smem_u32(smraw);
    const int tid = threadIdx.x;
    const int lane = tid & 31, wid = tid >> 5;
    const int wm = wid >> 2, wn = wid & 3;
    const int z = blockIdx.z;
    const int bm = blockIdx.y * 128, bn = blockIdx.x * 128;

    A += (size_t)z * CH * NPIX + (size_t)bm * NPIX;
    B += (size_t)z * NPIX * NPIX + (size_t)bn * NPIX;
    D += (size_t)z * CH * NPIX;

    {
        const float* SC = g_sc + (size_t)z * NBLK * NPIX + bn;
        float* sdst = (float*)smraw + (AVSC >> 2);
        #pragma unroll
        for (int t = 0; t < 16; t++) {
            int task = t * 256 + tid;
            int jbb = task >> 7, ii = task & 127;
            sdst[jbb * 128 + ii] = SC[(size_t)jbb * NPIX + ii];
        }
    }

    float acc[4][4][4];
    #pragma unroll
    for (int i = 0; i < 4; i++)
        #pragma unroll
        for (int j = 0; j < 4; j++)
            #pragma unroll
            for (int v = 0; v < 4; v++) acc[i][j][v] = 0.f;

    const int qrow = lane >> 2, qcol = lane & 3;
    const int S = NPIX / BK;   // 128

    load_av2(A, B, smbase, tid);
    CP_COMMIT();
    load_av2(A + BK, B + BK, smbase + AVBUF, tid);
    CP_COMMIT();

    uint32_t sreg[4];

    #pragma unroll 1
    for (int s = 0; s < S; s++) {
        CP_WAIT1();
        __syncthreads();
        if (s + 2 < S)
            load_av2(A + (s + 2) * BK, B + (s + 2) * BK,
                     smbase + (uint32_t)((s + 2) % 3) * AVBUF, tid);
        CP_COMMIT();

        if ((s & 3) == 0) {
            int jbb = s >> 2;
            #pragma unroll
            for (int nt = 0; nt < 4; nt++) {
                int cr = wn * 32 + nt * 8 + qrow;
                float sv;
                LDSF(sv, smbase + AVSC + (uint32_t)(jbb * 128 + cr) * 4);
                __half2 h2 = __float2half2_rn(sv);
                sreg[nt] = *(uint32_t*)&h2;
            }
        }

        uint32_t sa = smbase + (uint32_t)(s % 3) * AVBUF;
        uint32_t sb = sa + AVTILE;
        #pragma unroll
        for (int ks = 0; ks < 2; ks++) {
            const int kc = ks * 16 + qcol * 2;
            uint32_t af[4][4];
            #pragma unroll
            for (int mt = 0; mt < 4; mt++) {
                int r = wm * 64 + mt * 16 + qrow;
                LDS32(af[mt][0], sa + (uint32_t)(r * 80 + kc * 2));
                LDS32(af[mt][1], sa + (uint32_t)((r + 8) * 80 + kc * 2));
                LDS32(af[mt][2], sa + (uint32_t)(r * 80 + (kc + 8) * 2));
                LDS32(af[mt][3], sa + (uint32_t)((r + 8) * 80 + (kc + 8) * 2));
            }
            #pragma unroll
            for (int nt = 0; nt < 4; nt++) {
                int cr = wn * 32 + nt * 8 + qrow;
                uint32_t b0, b1;
                LDS32(b0, sb + (uint32_t)(cr * 80 + kc * 2));
                LDS32(b1, sb + (uint32_t)(cr * 80 + (kc + 8) * 2));
                __half2 hb0 = __hmul2(*(__half2*)&b0, *(__half2*)&sreg[nt]);
                __half2 hb1 = __hmul2(*(__half2*)&b1, *(__half2*)&sreg[nt]);
                b0 = *(uint32_t*)&hb0;
                b1 = *(uint32_t*)&hb1;
                #pragma unroll
                for (int mt = 0; mt < 4; mt++)
                    MMAH(acc[mt][nt], af[mt], b0, b1);
            }
        }
    }

    #pragma unroll
    for (int nt = 0; nt < 4; nt++) {
        int col = bn + wn * 32 + nt * 8 + qcol * 2;
        #pragma unroll
        for (int mt = 0; mt < 4; mt++) {
            int r0 = bm + wm * 64 + mt * 16 + qrow;
            *(float2*)&D[(size_t)r0 * NPIX + col] =
                make_float2(acc[mt][nt][0], acc[mt][nt][1]);
            *(float2*)&D[(size_t)(r0 + 8) * NPIX + col] =
                make_float2(acc[mt][nt][2], acc[mt][nt][3]);
        }
    }
}

// ---------------------------------------------------------------------------
// Packing kernels
// ---------------------------------------------------------------------------
__global__ __launch_bounds__(256) void pack_w_kernel(
    const float* __restrict__ wq, const float* __restrict__ wk,
    const float* __restrict__ wv)
{
    int i = blockIdx.x * 256 + threadIdx.x;
    g_wp[i]               = pack_split(wq[i]);
    g_wp[CH * CH + i]     = pack_split(wk[i]);
    g_wp[2 * CH * CH + i] = pack_split(wv[i]);
}

__global__ __launch_bounds__(256) void pack_xt_kernel(const float* __restrict__ x)
{
    __shared__ float t[32][33];
    const int b = blockIdx.z;
    const int n0 = blockIdx.x * 32, c0 = blockIdx.y * 32;
    const int tx = threadIdx.x, ty = threadIdx.y;
    const float* xb = x + (size_t)b * CH * NPIX;
    #pragma unroll
    for (int i = 0; i < 4; i++)
        t[ty * 4 + i][tx] = xb[(size_t)(c0 + ty * 4 + i) * NPIX + n0 + tx];
    __syncthreads();
    uint32_t* xt = g_xt + (size_t)b * NPIX * CH;
    #pragma unroll
    for (int i = 0; i < 4; i++)
        xt[(size_t)(n0 + ty * 4 + i) * CH + c0 + tx] = pack_split(t[tx][ty * 4 + i]);
}

// ---------------------------------------------------------------------------
extern "C" void kernel_launch(void* const* d_in, const int* in_sizes, int n_in,
                              void* d_out, int out_size)
{
    const float* x  = (const float*)d_in[0];
    const float* wq = (const float*)d_in[1];
    const float* bq = (const float*)d_in[2];
    const float* wk = (const float*)d_in[3];
    const float* bk = (const float*)d_in[4];
    const float* wv = (const float*)d_in[5];
    const float* bv = (const float*)d_in[6];
    float* out = (float*)d_out;

    void *pvh, *pah;
    cudaGetSymbolAddress(&pvh, g_vh);
    cudaGetSymbolAddress(&pah, g_ah);
    __half* vh = (__half*)pvh;
    __half* ah = (__half*)pah;

    cudaFuncSetAttribute(proj_kernel,    cudaFuncAttributeMaxDynamicSharedMemorySize, S2SMEM);
    cudaFuncSetAttribute(scores2_kernel, cudaFuncAttributeMaxDynamicSharedMemorySize, S2SMEM);
    cudaFuncSetAttribute(av3_kernel,     cudaFuncAttributeMaxDynamicSharedMemorySize, AVSMEM);

    pack_w_kernel<<<CH * CH / 256, 256>>>(wq, wk, wv);
    pack_xt_kernel<<<dim3(NPIX / 32, CH / 32, BATCH), dim3(32, 8)>>>(x);

    // All three projections in ONE launch (z = b*3 + which), 2 CTAs/SM
    proj_kernel<<<dim3(NPIX / 128, CH / 128, BATCH * 3), 256, S2SMEM>>>(bq, bk, bv);
    // scores + fused block softmax -> p, m_block, l_block
    scores2_kernel<<<dim3(NPIX / 128, NPIX / 128, BATCH), 256, S2SMEM>>>();
    // per-row global stats -> scale
    rowstats_kernel<<<BATCH * NPIX / 256, 256>>>();
    // out[c][i] = sum_j V[c][j] * p[i][j] * scale  (norm fused into AV)
    av3_kernel<<<dim3(NPIX / 128, CH / 128, BATCH), 256, AVSMEM>>>(vh, ah, out);
}